// round 1
// baseline (speedup 1.0000x reference)
#include <cuda_runtime.h>
#include <math.h>

#define NN 20000
#define DD 128
#define NE (NN*DD)          // 2,560,000
#define NEDGE 320000
#define LN_EPS 1e-5f
#define LAMW 0.1

// ---------------- device scratch (no allocations allowed) ----------------
__device__ float  g_pool[10*NE];      // F0..F7, Z7, ZNEW  (~102 MB)
__device__ int    g_counts[NN];
__device__ int    g_fill[NN];
__device__ int    g_rowptr[NN+1];
__device__ int    g_ecol[NEDGE];
__device__ float  g_eval[NEDGE];
__device__ double g_red[14];
__device__ float  g_gamma[4];
__device__ int    g_flag;

struct Win { const float4* z[5]; const float4* f[5]; };

// ---------------- CSR build ----------------
__global__ void k_zero_csr() {
    int i = blockIdx.x*blockDim.x + threadIdx.x;
    if (i < NN) { g_counts[i] = 0; g_fill[i] = 0; }
}

__global__ void k_count(const int* __restrict__ rows) {
    int e = blockIdx.x*blockDim.x + threadIdx.x;
    if (e < NEDGE) atomicAdd(&g_counts[rows[e]], 1);
}

__global__ void k_scan() {
    __shared__ int sh[1024];
    int t = threadIdx.x;
    const int CH = (NN + 1023) / 1024;   // 20
    int base = t * CH;
    int sum = 0;
    for (int k = 0; k < CH; k++) { int i = base + k; if (i < NN) sum += g_counts[i]; }
    sh[t] = sum;
    __syncthreads();
    for (int off = 1; off < 1024; off <<= 1) {
        int v = (t >= off) ? sh[t-off] : 0;
        __syncthreads();
        sh[t] += v;
        __syncthreads();
    }
    int offset = (t == 0) ? 0 : sh[t-1];
    for (int k = 0; k < CH; k++) {
        int i = base + k;
        if (i < NN) { g_rowptr[i] = offset; offset += g_counts[i]; }
    }
    if (t == 1023) g_rowptr[NN] = sh[1023];
}

__global__ void k_scatter(const int* __restrict__ rows, const int* __restrict__ cols,
                          const float* __restrict__ vals) {
    int e = blockIdx.x*blockDim.x + threadIdx.x;
    if (e < NEDGE) {
        int r = rows[e];
        int p = atomicAdd(&g_fill[r], 1);
        int idx = g_rowptr[r] + p;
        g_ecol[idx] = cols[e];
        g_eval[idx] = vals[e];
    }
}

// ---------------- fused diag*z + SpMM + layernorm, one warp per node ----------------
__global__ void k_spmm_ln(const float4* __restrict__ z, float4* __restrict__ out,
                          const float* __restrict__ diag,
                          const float4* __restrict__ w4, const float4* __restrict__ b4) {
    int gw   = (blockIdx.x*blockDim.x + threadIdx.x) >> 5;
    int lane = threadIdx.x & 31;
    if (gw >= NN) return;

    float dg  = diag[gw];
    float4 zc = z[gw*32 + lane];
    float4 acc = make_float4(dg*zc.x, dg*zc.y, dg*zc.z, dg*zc.w);

    int s = g_rowptr[gw], e = g_rowptr[gw+1];
    for (int j = s; j < e; j++) {
        float v = g_eval[j];
        int   c = g_ecol[j];
        float4 t = z[c*32 + lane];
        acc.x += v*t.x; acc.y += v*t.y; acc.z += v*t.z; acc.w += v*t.w;
    }

    // layernorm over the 128-dim row (warp collective)
    float ssum = acc.x + acc.y + acc.z + acc.w;
    #pragma unroll
    for (int off = 16; off; off >>= 1) ssum += __shfl_xor_sync(0xffffffffu, ssum, off);
    float mu = ssum * (1.0f/128.0f);

    float dx = acc.x - mu, dy = acc.y - mu, dz = acc.z - mu, dw = acc.w - mu;
    float vs = dx*dx + dy*dy + dz*dz + dw*dw;
    #pragma unroll
    for (int off = 16; off; off >>= 1) vs += __shfl_xor_sync(0xffffffffu, vs, off);
    float inv = rsqrtf(vs * (1.0f/128.0f) + LN_EPS);

    float4 wv = w4[lane], bv = b4[lane];
    float4 o = make_float4(wv.x*dx*inv + bv.x, wv.y*dy*inv + bv.y,
                           wv.z*dz*inv + bv.z, wv.w*dw*inv + bv.w);
    out[gw*32 + lane] = o;
}

// ---------------- Anderson acceleration ----------------
__global__ void k_zero_red() {
    int t = threadIdx.x;
    if (t < 14) g_red[t] = 0.0;
    if (t == 14) g_flag = 0;
}

// 14 fused dot products: Gram(dG) upper triangle (10) + dG^T g4 (4)
__global__ void k_dots(Win wi) {
    float s[14];
    #pragma unroll
    for (int j = 0; j < 14; j++) s[j] = 0.0f;

    int stride = gridDim.x * blockDim.x;
    for (int i = blockIdx.x*blockDim.x + threadIdx.x; i < NE/4; i += stride) {
        float4 g[5];
        #pragma unroll
        for (int k = 0; k < 5; k++) {
            float4 fz = wi.f[k][i];
            float4 zz = wi.z[k][i];
            g[k] = make_float4(fz.x-zz.x, fz.y-zz.y, fz.z-zz.z, fz.w-zz.w);
        }
        float4 dgv[4];
        #pragma unroll
        for (int m = 0; m < 4; m++)
            dgv[m] = make_float4(g[m+1].x-g[m].x, g[m+1].y-g[m].y,
                                 g[m+1].z-g[m].z, g[m+1].w-g[m].w);
        int c = 0;
        #pragma unroll
        for (int m = 0; m < 4; m++) {
            #pragma unroll
            for (int n = m; n < 4; n++) {
                s[c++] += dgv[m].x*dgv[n].x + dgv[m].y*dgv[n].y
                        + dgv[m].z*dgv[n].z + dgv[m].w*dgv[n].w;
            }
        }
        #pragma unroll
        for (int m = 0; m < 4; m++) {
            s[10+m] += dgv[m].x*g[4].x + dgv[m].y*g[4].y
                     + dgv[m].z*g[4].z + dgv[m].w*g[4].w;
        }
    }

    // block reduce: warp shfl (float) -> per-block double -> 1 atomic per sum
    __shared__ float red[14][8];
    int wid = threadIdx.x >> 5, lane = threadIdx.x & 31;
    #pragma unroll
    for (int j = 0; j < 14; j++) {
        float v = s[j];
        #pragma unroll
        for (int off = 16; off; off >>= 1) v += __shfl_xor_sync(0xffffffffu, v, off);
        if (lane == 0) red[j][wid] = v;
    }
    __syncthreads();
    if (threadIdx.x < 14) {
        double t = 0.0;
        #pragma unroll
        for (int k = 0; k < 8; k++) t += (double)red[threadIdx.x][k];
        atomicAdd(&g_red[threadIdx.x], t);
    }
}

// solve (dG^T dG + lam I) gamma = dG^T g4   (4x4, one thread)
__global__ void k_solve() {
    double H[4][4], rhs[4], gam[4];
    int c = 0;
    for (int m = 0; m < 4; m++)
        for (int n = m; n < 4; n++) { H[m][n] = H[n][m] = g_red[c++]; }
    for (int m = 0; m < 4; m++) rhs[m] = g_red[10+m];
    for (int m = 0; m < 4; m++) H[m][m] += LAMW;

    // gaussian elimination with partial pivoting
    for (int k = 0; k < 4; k++) {
        int p = k;
        for (int r = k+1; r < 4; r++) if (fabs(H[r][k]) > fabs(H[p][k])) p = r;
        if (p != k) {
            for (int cc = 0; cc < 4; cc++) { double t = H[k][cc]; H[k][cc] = H[p][cc]; H[p][cc] = t; }
            double t = rhs[k]; rhs[k] = rhs[p]; rhs[p] = t;
        }
        for (int r = k+1; r < 4; r++) {
            double fac = H[r][k] / H[k][k];
            for (int cc = k; cc < 4; cc++) H[r][cc] -= fac * H[k][cc];
            rhs[r] -= fac * rhs[k];
        }
    }
    for (int k = 3; k >= 0; k--) {
        double t = rhs[k];
        for (int cc = k+1; cc < 4; cc++) t -= H[k][cc] * gam[cc];
        gam[k] = t / H[k][k];
    }
    for (int m = 0; m < 4; m++) g_gamma[m] = (float)gam[m];
}

// z_new = F[:, -1] - dF @ gamma ; global finiteness flag
__global__ void k_znew(Win wi, float4* __restrict__ zn) {
    float gm[4];
    #pragma unroll
    for (int m = 0; m < 4; m++) gm[m] = g_gamma[m];

    int stride = gridDim.x * blockDim.x;
    for (int i = blockIdx.x*blockDim.x + threadIdx.x; i < NE/4; i += stride) {
        float4 f[5];
        #pragma unroll
        for (int k = 0; k < 5; k++) f[k] = wi.f[k][i];
        float4 a = f[4];
        #pragma unroll
        for (int m = 0; m < 4; m++) {
            a.x -= gm[m] * (f[m+1].x - f[m].x);
            a.y -= gm[m] * (f[m+1].y - f[m].y);
            a.z -= gm[m] * (f[m+1].z - f[m].z);
            a.w -= gm[m] * (f[m+1].w - f[m].w);
        }
        zn[i] = a;
        if (!(isfinite(a.x) && isfinite(a.y) && isfinite(a.z) && isfinite(a.w)))
            g_flag = 1;
    }
}

// z = all_finite ? 0.5*f_z + 0.5*z_new : f_z
__global__ void k_blend(const float4* __restrict__ fz, const float4* __restrict__ zn,
                        float4* __restrict__ out) {
    int i = blockIdx.x*blockDim.x + threadIdx.x;
    if (i < NE/4) {
        float4 f = fz[i];
        if (g_flag) {
            out[i] = f;
        } else {
            float4 z = zn[i];
            out[i] = make_float4(0.5f*(f.x+z.x), 0.5f*(f.y+z.y),
                                 0.5f*(f.z+z.z), 0.5f*(f.w+z.w));
        }
    }
}

// ---------------- host ----------------
extern "C" void kernel_launch(void* const* d_in, const int* in_sizes, int n_in,
                              void* d_out, int out_size) {
    const float*  x    = (const float*)d_in[0];
    const float*  diag = (const float*)d_in[1];
    const float*  vals = (const float*)d_in[2];
    const float4* w4   = (const float4*)d_in[3];
    const float4* b4   = (const float4*)d_in[4];
    const int*    rows = (const int*)d_in[5];
    const int*    cols = (const int*)d_in[6];
    // d_in[7]=batch (unused), d_in[8]=max_iter (fixed at 8 for this problem)

    float* pool = nullptr;
    cudaGetSymbolAddress((void**)&pool, g_pool);
    float* F[8];
    for (int i = 0; i < 8; i++) F[i] = pool + (size_t)i * NE;
    float* Z7 = pool + (size_t)8 * NE;
    float* ZN = pool + (size_t)9 * NE;

    // CSR build (recomputed every launch; deterministic work)
    k_zero_csr<<<(NN+255)/256, 256>>>();
    k_count  <<<(NEDGE+255)/256, 256>>>(rows);
    k_scan   <<<1, 1024>>>();
    k_scatter<<<(NEDGE+255)/256, 256>>>(rows, cols, vals);

    const float* z = x;
    for (int i = 0; i < 8; i++) {
        k_spmm_ln<<<(NN*32+255)/256, 256>>>((const float4*)z, (float4*)F[i], diag, w4, b4);
        if (i < 6) {
            z = F[i];
        } else {
            // history window after append at iteration i: z_{i-4..i}, F_{i-4..i}
            // z_0 = x, z_j = F_{j-1} for j=1..6, z_7 = Z7
            Win wi;
            for (int k = 0; k < 5; k++) {
                int j = i - 4 + k;
                const float* zj = (j == 0) ? x : ((j == 7) ? Z7 : F[j-1]);
                wi.z[k] = (const float4*)zj;
                wi.f[k] = (const float4*)F[j];
            }
            k_zero_red<<<1, 32>>>();
            k_dots   <<<512, 256>>>(wi);
            k_solve  <<<1, 1>>>();
            k_znew   <<<512, 256>>>(wi, (float4*)ZN);
            float* dst = (i == 7) ? (float*)d_out : Z7;
            k_blend  <<<(NE/4 + 255)/256, 256>>>((const float4*)F[i], (const float4*)ZN,
                                                 (float4*)dst);
            z = dst;
        }
    }
}